// round 16
// baseline (speedup 1.0000x reference)
#include <cuda_runtime.h>
#include <cstdint>

#define NC   3144   // counties
#define TT   156    // time steps
#define TP   154    // predicted steps (T - p)
#define TPAD 160    // padded t dimension
#define NNZ  31440
#define CAP  128    // bucket capacity (Poisson(10), max ~35)

#define NOUT (2 * TP * NC)              // 968352 output floats
#define KA_SCAT  123                    // ceil(NNZ/256)
#define KA_COV   13                     // ceil(NC/256)
#define NMT2 25                         // m-tiles of 128
#define KA_TRANS (NMT2 * 5)             // 125 (128m x 32t tiles)
#define KA_BLOCKS (KA_SCAT + KA_COV + KA_TRANS)

#define GATH_BLOCKS 393                 // NC/8
#define BASE_BLOCKS 260                 // 13 m-groups x 20 t-chunks
#define KBC_BLOCKS  (GATH_BLOCKS + BASE_BLOCKS)

// ---- scratch (zero-initialized at load; meta slots >= cnt stay zero) ----
__device__ int    g_count[NC];
__device__ int4   g_meta[NC * CAP];   // {row, bv, av, hv}; pad slots = 0
__device__ float2 g_csd[NC * TPAD];   // {cs, ds} fp32 at [m][t]
__device__ float2 g_covb[NC];         // {ups@cov, zeta@cov}
__device__ float  g_gth[NOUT];        // gather result, out layout

// ============================================================
// Kernel A (256 thr): scatter (123) + covb (13) + csd
// transpose (125 blocks of 128m x 32t -> deep per-thread MLP).
// ============================================================
__global__ void kA_kernel(
    const float* __restrict__ C, const float* __restrict__ D,
    const float* __restrict__ cov,
    const float* __restrict__ ups, const float* __restrict__ zeta,
    const float* __restrict__ bnz, const float* __restrict__ anz,
    const float* __restrict__ hnz, const int* __restrict__ rows,
    const int* __restrict__ cols)
{
    const int b = blockIdx.x, tid = threadIdx.x;

    if (b < KA_SCAT) {
        int k = b * 256 + tid;
        if (k < NNZ) {
            int c = cols[k];
            int slot = atomicAdd(&g_count[c], 1);
            if (slot < CAP)
                g_meta[c * CAP + slot] = make_int4(
                    rows[k], __float_as_int(bnz[k]),
                    __float_as_int(anz[k]), __float_as_int(hnz[k]));
        }
        return;
    }

    if (b < KA_SCAT + KA_COV) {          // covariate dot products
        int m = (b - KA_SCAT) * 256 + tid;
        if (m < NC) {
            float a = 0.f, z = 0.f;
#pragma unroll
            for (int j = 0; j < 10; j++) {
                float cvv = cov[j * NC + m];
                a += ups[j]  * cvv;
                z += zeta[j] * cvv;
            }
            g_covb[m] = make_float2(a, z);
        }
        return;
    }

    // ---------------- transpose: 128m x 32t tile ----------------
    __shared__ float sC[33][129], sD[33][129];   // pad 129: conflict-free
    const int tb = b - KA_SCAT - KA_COV;
    const int m0 = (tb % NMT2) * 128, t0 = (tb / NMT2) * 32;

    // load: 33 t-rows x 128 m, coalesced; ~17 independent iters x 2 loads
#pragma unroll
    for (int i = 0; i < 17; i++) {
        int idx = i * 256 + tid;
        if (idx < 33 * 128) {
            int r = idx >> 7, cm = idx & 127;
            int tg = min(t0 + r, TT - 1);
            int mg = min(m0 + cm, NC - 1);
            sC[r][cm] = C[tg * NC + mg];
            sD[r][cm] = D[tg * NC + mg];
        }
    }
    __syncthreads();

    // store: warp w owns m-cols w*16..w*16+15; lane = t offset.
    // Each (warp, ml) writes a contiguous 256B float2 run.
    const int lane = tid & 31, w = tid >> 5;
#pragma unroll
    for (int i = 0; i < 16; i++) {
        int ml = w * 16 + i;
        int mg = m0 + ml;
        if (mg < NC) {
            float cs = sC[lane][ml] + sC[lane + 1][ml];
            float ds = sD[lane][ml] + sD[lane + 1][ml];
            g_csd[mg * TPAD + t0 + lane] = make_float2(cs, ds);
        }
    }
}

// ============================================================
// Kernel BC (256 thr, 653 blocks): FUSED gather + base.
// Blocks 0..392: sparse gather (R4 shape) -> g_gth.
// Blocks 393..652: mobility + covariate base -> out.
// (Heterogeneous co-scheduling: measured win in R14.)
// ============================================================
__global__ void __launch_bounds__(256) kBC_kernel(
    const float* __restrict__ M, const float* __restrict__ mu,
    const float* __restrict__ nu, float* __restrict__ out)
{
    const int tid = threadIdx.x;

    if (blockIdx.x < GATH_BLOCKS) {
        // ---------------- sparse gather ----------------
        __shared__ int4   smeta[8][32];
        __shared__ int    scnt[8];
        __shared__ float2 tile[TPAD][9];      // [t][m_local], padded

        const int w    = tid >> 5, lane = tid & 31;
        const int m0   = blockIdx.x * 8;
        const int m    = m0 + w;              // NC = 393*8 exact

        smeta[tid >> 5][tid & 31] = g_meta[(m0 + (tid >> 5)) * CAP + (tid & 31)];
        if (tid < 8) scnt[tid] = g_count[m0 + tid];
        __syncthreads();
        if (tid < 8) g_count[m0 + tid] = 0;   // re-arm for graph replay

        const int cnt = scnt[w];
        const float2* __restrict__ csd = g_csd;

        float accC[5] = {0.f, 0.f, 0.f, 0.f, 0.f};
        float accD[5] = {0.f, 0.f, 0.f, 0.f, 0.f};

        const int jn = min(cnt, 32);
#pragma unroll 2
        for (int j = 0; j < jn; j++) {
            int4 md = smeta[w][j];            // LDS broadcast
            const float2* __restrict__ cr = &csd[md.x * TPAD + lane];
            float bv = __int_as_float(md.y);
            float av = __int_as_float(md.z);
            float hv = __int_as_float(md.w);
            float2 v0 = cr[0], v1 = cr[32], v2 = cr[64], v3 = cr[96], v4 = cr[128];
            accC[0] += bv * v0.x;  accD[0] += hv * v0.x + av * v0.y;
            accC[1] += bv * v1.x;  accD[1] += hv * v1.x + av * v1.y;
            accC[2] += bv * v2.x;  accD[2] += hv * v2.x + av * v2.y;
            accC[3] += bv * v3.x;  accD[3] += hv * v3.x + av * v3.y;
            accC[4] += bv * v4.x;  accD[4] += hv * v4.x + av * v4.y;
        }
        for (int s = 32; s < cnt; s++) {      // rare tail
            int4 md = g_meta[m * CAP + s];
            const float2* __restrict__ cr = &csd[md.x * TPAD + lane];
            float bv = __int_as_float(md.y);
            float av = __int_as_float(md.z);
            float hv = __int_as_float(md.w);
#pragma unroll
            for (int i = 0; i < 5; i++) {
                float2 v = cr[32 * i];
                accC[i] += bv * v.x;
                accD[i] += hv * v.x + av * v.y;
            }
        }

#pragma unroll
        for (int i = 0; i < 5; i++)
            tile[lane + 32 * i][w] = make_float2(accC[i], accD[i]);
        __syncthreads();

#pragma unroll
        for (int i = 0; i < 10; i++) {
            int idx = tid + i * 256;          // < 2560
            int t = idx >> 3, mo = idx & 7;
            if (t < TP) {
                float2 v = tile[t][mo];
                g_gth[t        * NC + m0 + mo] = v.x;
                g_gth[(TP + t) * NC + m0 + mo] = v.y;
            }
        }
    } else {
        // ---------------- mobility + covariate base ----------------
        const int bb = blockIdx.x - GATH_BLOCKS;
        const int mgrp = bb % 13, chunk = bb / 13;
        const int m = mgrp * 256 + tid;
        if (m >= NC) return;
        const int t0 = chunk * 8;

        float2 cvb = g_covb[m];
        float muv[12], nuv[12];
#pragma unroll
        for (int i = 0; i < 12; i++) { muv[i] = mu[i]; nuv[i] = nu[i]; }

        float mn[6];
#pragma unroll
        for (int k = 0; k < 6; k++) mn[k] = M[(k * TT + t0) * NC + m];

#pragma unroll
        for (int j = 0; j < 8; j++) {
            int t = t0 + j;
            int tn = min(t + 1, TT - 1);
            float mc = cvb.x, md = cvb.y;
#pragma unroll
            for (int k = 0; k < 6; k++) {
                float v0 = mn[k];
                float v1 = M[(k * TT + tn) * NC + m];
                mn[k] = v1;
                mc += muv[k*2] * v0 + muv[k*2+1] * v1;
                md += nuv[k*2] * v0 + nuv[k*2+1] * v1;
            }
            if (t < TP) {
                out[t        * NC + m] = mc;
                out[(TP + t) * NC + m] = md;
            }
        }
    }
}

// ============================================================
// Kernel D: join — out += gather. float4 over 968352 floats.
// ============================================================
__global__ void kD_kernel(float* __restrict__ out)
{
    int idx = blockIdx.x * 256 + threadIdx.x;
    if (idx < NOUT / 4) {
        float4 o = reinterpret_cast<float4*>(out)[idx];
        float4 g = reinterpret_cast<const float4*>(g_gth)[idx];
        o.x += g.x; o.y += g.y; o.z += g.z; o.w += g.w;
        reinterpret_cast<float4*>(out)[idx] = o;
    }
}

// ============================================================
extern "C" void kernel_launch(void* const* d_in, const int* in_sizes, int n_in,
                              void* d_out, int out_size)
{
    const float* C    = (const float*)d_in[0];
    const float* D    = (const float*)d_in[1];
    const float* M    = (const float*)d_in[2];
    const float* cov  = (const float*)d_in[3];
    const float* bnz  = (const float*)d_in[4];
    const float* anz  = (const float*)d_in[5];
    const float* hnz  = (const float*)d_in[6];
    const float* mu   = (const float*)d_in[7];
    const float* nu   = (const float*)d_in[8];
    const float* ups  = (const float*)d_in[9];
    const float* zeta = (const float*)d_in[10];
    const int*   rows = (const int*)d_in[11];
    const int*   cols = (const int*)d_in[12];
    float* out = (float*)d_out;

    kA_kernel<<<KA_BLOCKS, 256>>>(C, D, cov, ups, zeta,
                                  bnz, anz, hnz, rows, cols);
    kBC_kernel<<<KBC_BLOCKS, 256>>>(M, mu, nu, out);
    kD_kernel<<<(NOUT / 4 + 255) / 256, 256>>>(out);
}

// round 17
// speedup vs baseline: 1.0388x; 1.0388x over previous
#include <cuda_runtime.h>
#include <cstdint>

#define NC   3144   // counties
#define TT   156    // time steps
#define TP   154    // predicted steps (T - p)
#define TPAD 160    // padded t dimension
#define NNZ  31440
#define CAP  128    // bucket capacity (Poisson(10), max ~35)

#define NOUT (2 * TP * NC)              // 968352 output floats
#define NMT  99                         // m-tiles of 32 for the transpose
#define KA_SCAT  31                     // ceil(NNZ/1024)
#define KA_COV   4                      // ceil(NC/1024)
#define KA_TRANS (NMT * 5)              // 495
#define KA_BLOCKS (KA_SCAT + KA_COV + KA_TRANS)   // 530

#define GATH_BLOCKS 393                 // NC/8
#define BASE_BLOCKS 260                 // 13 m-groups x 20 t-chunks
#define KBC_BLOCKS  (GATH_BLOCKS + BASE_BLOCKS)

// ---- scratch (zero-initialized at load; meta slots >= cnt stay zero) ----
__device__ int    g_count[NC];
__device__ int4   g_meta[NC * CAP];   // {row, bv, av, hv}; pad slots = 0
__device__ float2 g_csd[NC * TPAD];   // {cs, ds} fp32 at [m][t]
__device__ float2 g_covb[NC];         // {ups@cov, zeta@cov}
__device__ float  g_gth[NOUT];        // gather result, out layout

// ============================================================
// Kernel A (1024 thr, 530 blocks): scatter (31) + covb (4) +
// csd transpose (495; 32m x 32t tile, 1 elem/thread).
// R9-measured shape: ~2.7 us.
// ============================================================
__global__ void kA_kernel(
    const float* __restrict__ C, const float* __restrict__ D,
    const float* __restrict__ cov,
    const float* __restrict__ ups, const float* __restrict__ zeta,
    const float* __restrict__ bnz, const float* __restrict__ anz,
    const float* __restrict__ hnz, const int* __restrict__ rows,
    const int* __restrict__ cols)
{
    const int b = blockIdx.x, tid = threadIdx.x;

    if (b < KA_SCAT) {
        int k = b * 1024 + tid;
        if (k < NNZ) {
            int c = cols[k];
            int slot = atomicAdd(&g_count[c], 1);
            if (slot < CAP)
                g_meta[c * CAP + slot] = make_int4(
                    rows[k], __float_as_int(bnz[k]),
                    __float_as_int(anz[k]), __float_as_int(hnz[k]));
        }
        return;
    }

    if (b < KA_SCAT + KA_COV) {          // covariate dot products
        int m = (b - KA_SCAT) * 1024 + tid;
        if (m < NC) {
            float a = 0.f, z = 0.f;
#pragma unroll
            for (int j = 0; j < 10; j++) {
                float cvv = cov[j * NC + m];
                a += ups[j]  * cvv;
                z += zeta[j] * cvv;
            }
            g_covb[m] = make_float2(a, z);
        }
        return;
    }

    // ---- transpose tile: rows t0..t0+32 (33), cols m0..m0+31 ----
    __shared__ float sC[33][33], sD[33][33];
    const int tb = b - KA_SCAT - KA_COV;
    const int m0 = (tb % NMT) * 32, t0 = (tb / NMT) * 32;

    for (int idx = tid; idx < 33 * 32; idx += 1024) {
        int r = idx >> 5, cm = idx & 31;
        int tg = min(t0 + r, TT - 1);
        int mg = min(m0 + cm, NC - 1);
        sC[r][cm] = C[tg * NC + mg];
        sD[r][cm] = D[tg * NC + mg];
    }
    __syncthreads();

    const int tx = tid & 31, ty = tid >> 5;   // tx = t offset, ty = m offset
    const int mg = m0 + ty;
    if (mg < NC) {
        float cs = sC[tx][ty] + sC[tx + 1][ty];
        float ds = sD[tx][ty] + sD[tx + 1][ty];
        g_csd[mg * TPAD + t0 + tx] = make_float2(cs, ds);
    }
}

// ============================================================
// Kernel BC (256 thr, 653 blocks): FUSED gather + base.
// Blocks 0..392: sparse gather (R4 shape) -> g_gth.
// Blocks 393..652: mobility + covariate base -> out.
// (Heterogeneous co-scheduling: measured win in R14, ~8.2 us.)
// ============================================================
__global__ void __launch_bounds__(256) kBC_kernel(
    const float* __restrict__ M, const float* __restrict__ mu,
    const float* __restrict__ nu, float* __restrict__ out)
{
    const int tid = threadIdx.x;

    if (blockIdx.x < GATH_BLOCKS) {
        // ---------------- sparse gather ----------------
        __shared__ int4   smeta[8][32];
        __shared__ int    scnt[8];
        __shared__ float2 tile[TPAD][9];      // [t][m_local], padded

        const int w    = tid >> 5, lane = tid & 31;
        const int m0   = blockIdx.x * 8;
        const int m    = m0 + w;              // NC = 393*8 exact

        smeta[tid >> 5][tid & 31] = g_meta[(m0 + (tid >> 5)) * CAP + (tid & 31)];
        if (tid < 8) scnt[tid] = g_count[m0 + tid];
        __syncthreads();
        if (tid < 8) g_count[m0 + tid] = 0;   // re-arm for graph replay

        const int cnt = scnt[w];
        const float2* __restrict__ csd = g_csd;

        float accC[5] = {0.f, 0.f, 0.f, 0.f, 0.f};
        float accD[5] = {0.f, 0.f, 0.f, 0.f, 0.f};

        const int jn = min(cnt, 32);
#pragma unroll 2
        for (int j = 0; j < jn; j++) {
            int4 md = smeta[w][j];            // LDS broadcast
            const float2* __restrict__ cr = &csd[md.x * TPAD + lane];
            float bv = __int_as_float(md.y);
            float av = __int_as_float(md.z);
            float hv = __int_as_float(md.w);
            float2 v0 = cr[0], v1 = cr[32], v2 = cr[64], v3 = cr[96], v4 = cr[128];
            accC[0] += bv * v0.x;  accD[0] += hv * v0.x + av * v0.y;
            accC[1] += bv * v1.x;  accD[1] += hv * v1.x + av * v1.y;
            accC[2] += bv * v2.x;  accD[2] += hv * v2.x + av * v2.y;
            accC[3] += bv * v3.x;  accD[3] += hv * v3.x + av * v3.y;
            accC[4] += bv * v4.x;  accD[4] += hv * v4.x + av * v4.y;
        }
        for (int s = 32; s < cnt; s++) {      // rare tail
            int4 md = g_meta[m * CAP + s];
            const float2* __restrict__ cr = &csd[md.x * TPAD + lane];
            float bv = __int_as_float(md.y);
            float av = __int_as_float(md.z);
            float hv = __int_as_float(md.w);
#pragma unroll
            for (int i = 0; i < 5; i++) {
                float2 v = cr[32 * i];
                accC[i] += bv * v.x;
                accD[i] += hv * v.x + av * v.y;
            }
        }

#pragma unroll
        for (int i = 0; i < 5; i++)
            tile[lane + 32 * i][w] = make_float2(accC[i], accD[i]);
        __syncthreads();

#pragma unroll
        for (int i = 0; i < 10; i++) {
            int idx = tid + i * 256;          // < 2560
            int t = idx >> 3, mo = idx & 7;
            if (t < TP) {
                float2 v = tile[t][mo];
                g_gth[t        * NC + m0 + mo] = v.x;
                g_gth[(TP + t) * NC + m0 + mo] = v.y;
            }
        }
    } else {
        // ---------------- mobility + covariate base ----------------
        const int bb = blockIdx.x - GATH_BLOCKS;
        const int mgrp = bb % 13, chunk = bb / 13;
        const int m = mgrp * 256 + tid;
        if (m >= NC) return;
        const int t0 = chunk * 8;

        float2 cvb = g_covb[m];
        float muv[12], nuv[12];
#pragma unroll
        for (int i = 0; i < 12; i++) { muv[i] = mu[i]; nuv[i] = nu[i]; }

        float mn[6];
#pragma unroll
        for (int k = 0; k < 6; k++) mn[k] = M[(k * TT + t0) * NC + m];

#pragma unroll
        for (int j = 0; j < 8; j++) {
            int t = t0 + j;
            int tn = min(t + 1, TT - 1);
            float mc = cvb.x, md = cvb.y;
#pragma unroll
            for (int k = 0; k < 6; k++) {
                float v0 = mn[k];
                float v1 = M[(k * TT + tn) * NC + m];
                mn[k] = v1;
                mc += muv[k*2] * v0 + muv[k*2+1] * v1;
                md += nuv[k*2] * v0 + nuv[k*2+1] * v1;
            }
            if (t < TP) {
                out[t        * NC + m] = mc;
                out[(TP + t) * NC + m] = md;
            }
        }
    }
}

// ============================================================
// Kernel D: join — out += gather. float4 over 968352 floats.
// ============================================================
__global__ void kD_kernel(float* __restrict__ out)
{
    int idx = blockIdx.x * 256 + threadIdx.x;
    if (idx < NOUT / 4) {
        float4 o = reinterpret_cast<float4*>(out)[idx];
        float4 g = reinterpret_cast<const float4*>(g_gth)[idx];
        o.x += g.x; o.y += g.y; o.z += g.z; o.w += g.w;
        reinterpret_cast<float4*>(out)[idx] = o;
    }
}

// ============================================================
extern "C" void kernel_launch(void* const* d_in, const int* in_sizes, int n_in,
                              void* d_out, int out_size)
{
    const float* C    = (const float*)d_in[0];
    const float* D    = (const float*)d_in[1];
    const float* M    = (const float*)d_in[2];
    const float* cov  = (const float*)d_in[3];
    const float* bnz  = (const float*)d_in[4];
    const float* anz  = (const float*)d_in[5];
    const float* hnz  = (const float*)d_in[6];
    const float* mu   = (const float*)d_in[7];
    const float* nu   = (const float*)d_in[8];
    const float* ups  = (const float*)d_in[9];
    const float* zeta = (const float*)d_in[10];
    const int*   rows = (const int*)d_in[11];
    const int*   cols = (const int*)d_in[12];
    float* out = (float*)d_out;

    kA_kernel<<<KA_BLOCKS, 1024>>>(C, D, cov, ups, zeta,
                                   bnz, anz, hnz, rows, cols);
    kBC_kernel<<<KBC_BLOCKS, 256>>>(M, mu, nu, out);
    kD_kernel<<<(NOUT / 4 + 255) / 256, 256>>>(out);
}